// round 11
// baseline (speedup 1.0000x reference)
#include <cuda_runtime.h>
#include <cuda_bf16.h>
#include <math.h>
#include <stdint.h>

#define BSZ    4
#define LEN    2048
#define DMODEL 1024
#define DINNER 2048
#define DHALF  1024
#define NROWS  (BSZ * LEN)   // 8192
#define XDBL_W 96
#define DTRANK 64

// ---------------- scratch (static device globals: allocation-free) ----------
__device__ __align__(16) float g_xz[(size_t)NROWS * DINNER];
__device__ __align__(16) float g_u[(size_t)NROWS * DHALF];
__device__ __align__(16) float g_xdbl[(size_t)NROWS * XDBL_W];
__device__ __align__(16) float g_delta[(size_t)NROWS * DHALF];

// bf16 hi/mid activations
__device__ __align__(16) __nv_bfloat16 g_xh[(size_t)NROWS * DMODEL];
__device__ __align__(16) __nv_bfloat16 g_xm[(size_t)NROWS * DMODEL];
__device__ __align__(16) __nv_bfloat16 g_uh[(size_t)NROWS * DHALF];
__device__ __align__(16) __nv_bfloat16 g_um[(size_t)NROWS * DHALF];
__device__ __align__(16) __nv_bfloat16 g_ych[(size_t)NROWS * DINNER];
__device__ __align__(16) __nv_bfloat16 g_ycm[(size_t)NROWS * DINNER];
__device__ __align__(16) __nv_bfloat16 g_dtlh[(size_t)NROWS * DTRANK];
__device__ __align__(16) __nv_bfloat16 g_dtlm[(size_t)NROWS * DTRANK];

// pre-split transposed weights: [N][K] bf16, hi + mid levels
__device__ __align__(16) __nv_bfloat16 g_Win_h[(size_t)DINNER * DMODEL];
__device__ __align__(16) __nv_bfloat16 g_Win_m[(size_t)DINNER * DMODEL];
__device__ __align__(16) __nv_bfloat16 g_Wxd_h[(size_t)XDBL_W * DHALF];
__device__ __align__(16) __nv_bfloat16 g_Wxd_m[(size_t)XDBL_W * DHALF];
__device__ __align__(16) __nv_bfloat16 g_Wdt_h[(size_t)DHALF * DTRANK];
__device__ __align__(16) __nv_bfloat16 g_Wdt_m[(size_t)DHALF * DTRANK];
__device__ __align__(16) __nv_bfloat16 g_Wout_h[(size_t)DMODEL * DINNER];
__device__ __align__(16) __nv_bfloat16 g_Wout_m[(size_t)DMODEL * DINNER];

// ---------------- helpers ---------------------------------------------------
__device__ __forceinline__ void bsplit(float v, __nv_bfloat16& h, __nv_bfloat16& m) {
    h = __float2bfloat16_rn(v);
    m = __float2bfloat16_rn(v - __bfloat162float(h));
}
__device__ __forceinline__ void mma16(float* c, const unsigned* a, const unsigned* b) {
    asm volatile(
        "mma.sync.aligned.m16n8k16.row.col.f32.bf16.bf16.f32 "
        "{%0,%1,%2,%3}, {%4,%5,%6,%7}, {%8,%9}, {%0,%1,%2,%3};\n"
        : "+f"(c[0]), "+f"(c[1]), "+f"(c[2]), "+f"(c[3])
        : "r"(a[0]), "r"(a[1]), "r"(a[2]), "r"(a[3]), "r"(b[0]), "r"(b[1]));
}
__device__ __forceinline__ void ldsm4(unsigned* r, unsigned saddr) {
    asm volatile("ldmatrix.sync.aligned.m8n8.x4.shared.b16 {%0,%1,%2,%3}, [%4];"
        : "=r"(r[0]), "=r"(r[1]), "=r"(r[2]), "=r"(r[3]) : "r"(saddr));
}
__device__ __forceinline__ void cp16(unsigned s, const void* g, unsigned srcsz) {
    asm volatile("cp.async.cg.shared.global [%0], [%1], 16, %2;"
        :: "r"(s), "l"(g), "r"(srcsz) : "memory");
}
#define CP_COMMIT() asm volatile("cp.async.commit_group;" ::: "memory")
#define CP_WAIT1()  asm volatile("cp.async.wait_group 1;" ::: "memory")

// ---------------- weight transpose + bf16 hi/mid split ----------------------
__global__ void tsplit(const float* __restrict__ W, __nv_bfloat16* __restrict__ Th,
                       __nv_bfloat16* __restrict__ Tm, int K, int N)
{
    __shared__ float tile[32][33];
    const int n0 = blockIdx.x * 32, k0 = blockIdx.y * 32;
    const int tx = threadIdx.x, ty = threadIdx.y;   // 32 x 8
#pragma unroll
    for (int i = 0; i < 32; i += 8)
        tile[ty + i][tx] = W[(size_t)(k0 + ty + i) * N + n0 + tx];
    __syncthreads();
#pragma unroll
    for (int i = 0; i < 32; i += 8) {
        const float v = tile[tx][ty + i];
        __nv_bfloat16 h, m;
        bsplit(v, h, m);
        const size_t o = (size_t)(n0 + ty + i) * K + k0 + tx;
        Th[o] = h;
        Tm[o] = m;
    }
}

// ---------------- activation fp32 -> bf16 hi/mid split ----------------------
__global__ void asplit(const float* __restrict__ in, __nv_bfloat16* __restrict__ H,
                       __nv_bfloat16* __restrict__ M)
{
    const size_t i = (size_t)blockIdx.x * blockDim.x + threadIdx.x;  // float4 idx
    const float4 v = ((const float4*)in)[i];
    __nv_bfloat16 h0, h1, h2, h3, m0, m1, m2, m3;
    bsplit(v.x, h0, m0); bsplit(v.y, h1, m1);
    bsplit(v.z, h2, m2); bsplit(v.w, h3, m3);
    ((ushort4*)H)[i] = make_ushort4(__bfloat16_as_ushort(h0), __bfloat16_as_ushort(h1),
                                    __bfloat16_as_ushort(h2), __bfloat16_as_ushort(h3));
    ((ushort4*)M)[i] = make_ushort4(__bfloat16_as_ushort(m0), __bfloat16_as_ushort(m1),
                                    __bfloat16_as_ushort(m2), __bfloat16_as_ushort(m3));
}

// ================= cp.async double-buffered bf16 3-term split GEMM ==========
// C[M,N] = (Ah+Am)[M,K] @ (Bh+Bm)^T[N,K] (3 terms: hh + hm + mh).
// Block tile 128x128x16, 2-stage cp.async pipeline, 256 threads,
// 8 warps = 2(m) x 4(n), warp tile 64x32. Static smem 48 KB exactly.
// mode: 0 plain fp32, 1 +bias, 2 softplus(acc+2*bias),
//       3 fp32 + bf16 hi/mid of cols<64 into auxh/auxm (pitch 64).
#define BKC 16
#define PT  24   // bf16 pitch: 48B rows -> LDSM conflict-free, cp.async 16B aligned

__global__ __launch_bounds__(256)
void gemm_cs(const __nv_bfloat16* __restrict__ Ah, const __nv_bfloat16* __restrict__ Am,
             const __nv_bfloat16* __restrict__ Bh, const __nv_bfloat16* __restrict__ Bm,
             float* __restrict__ C, const float* __restrict__ bias,
             __nv_bfloat16* __restrict__ auxh, __nv_bfloat16* __restrict__ auxm,
             int N, int K, int ldc, int mode)
{
    __shared__ __align__(16) __nv_bfloat16 sAh[2][128 * PT];
    __shared__ __align__(16) __nv_bfloat16 sAm[2][128 * PT];
    __shared__ __align__(16) __nv_bfloat16 sBh[2][128 * PT];
    __shared__ __align__(16) __nv_bfloat16 sBm[2][128 * PT];

    const int tid  = threadIdx.x;
    const int lane = tid & 31;
    const int warp = tid >> 5;
    const int g = lane >> 2, q = lane & 3;
    const int wm = (warp & 1) * 64;
    const int wn = (warp >> 1) * 32;
    const int brow0 = blockIdx.y * 128;
    const int bcol0 = blockIdx.x * 128;

    // cp.async mapping: row r = tid>>1, k-half hh = tid&1 (8 bf16 = 16B)
    const int r  = tid >> 1;
    const int hh = tid & 1;
    const __nv_bfloat16* gAh = Ah + (size_t)(brow0 + r) * K + hh * 8;
    const __nv_bfloat16* gAm = Am + (size_t)(brow0 + r) * K + hh * 8;
    const int bn = bcol0 + r;
    const unsigned bsz = (bn < N) ? 16u : 0u;
    const size_t bro = (size_t)((bn < N) ? bn : 0) * K + hh * 8;
    const __nv_bfloat16* gBh = Bh + bro;
    const __nv_bfloat16* gBm = Bm + bro;

    const unsigned so = (r * PT + hh * 8) * 2;   // smem byte offset
    unsigned dAh[2], dAm[2], dBh[2], dBm[2];
#pragma unroll
    for (int s = 0; s < 2; s++) {
        dAh[s] = (unsigned)__cvta_generic_to_shared(sAh[s]) + so;
        dAm[s] = (unsigned)__cvta_generic_to_shared(sAm[s]) + so;
        dBh[s] = (unsigned)__cvta_generic_to_shared(sBh[s]) + so;
        dBm[s] = (unsigned)__cvta_generic_to_shared(sBm[s]) + so;
    }

    // ldmatrix lane offsets (bytes, no stage base)
    const int a_lr = (lane & 7) + ((lane >> 3) & 1) * 8;
    const int a_lc = (lane >> 4) * 8;
    const int b_lr = (lane & 7) + (lane >> 4) * 8;
    const int b_lc = ((lane >> 3) & 1) * 8;
    const unsigned aLo = ((wm + a_lr) * PT + a_lc) * 2;
    const unsigned bLo = ((wn + b_lr) * PT + b_lc) * 2;
    unsigned aBh[2], aBm[2], bBh[2], bBm[2];
#pragma unroll
    for (int s = 0; s < 2; s++) {
        aBh[s] = (unsigned)__cvta_generic_to_shared(sAh[s]) + aLo;
        aBm[s] = (unsigned)__cvta_generic_to_shared(sAm[s]) + aLo;
        bBh[s] = (unsigned)__cvta_generic_to_shared(sBh[s]) + bLo;
        bBm[s] = (unsigned)__cvta_generic_to_shared(sBm[s]) + bLo;
    }

    float acc[16][4];
#pragma unroll
    for (int i = 0; i < 16; i++)
#pragma unroll
        for (int j = 0; j < 4; j++) acc[i][j] = 0.f;

    const int niter = K / BKC;

    // prologue: issue stages 0,1
#pragma unroll
    for (int p = 0; p < 2; p++) {
        if (p < niter) {
            const int k0 = p * BKC;
            cp16(dAh[p], gAh + k0, 16);
            cp16(dAm[p], gAm + k0, 16);
            cp16(dBh[p], gBh + k0, bsz);
            cp16(dBm[p], gBm + k0, bsz);
        }
        CP_COMMIT();
    }

    for (int i = 0; i < niter; i++) {
        const int st = i & 1;
        CP_WAIT1();
        __syncthreads();

        // ---- compute stage st ----
        unsigned bhf[2][4], bmf[2][4];
        ldsm4(bhf[0], bBh[st]);
        ldsm4(bhf[1], bBh[st] + 16 * PT * 2);
        ldsm4(bmf[0], bBm[st]);
        ldsm4(bmf[1], bBm[st] + 16 * PT * 2);
#pragma unroll
        for (int m2 = 0; m2 < 4; m2++) {
            unsigned ah[4], am[4];
            ldsm4(ah, aBh[st] + m2 * (16 * PT * 2));
            ldsm4(am, aBm[st] + m2 * (16 * PT * 2));
#pragma unroll
            for (int p = 0; p < 2; p++) {
                float* c0 = acc[m2 * 4 + 2 * p];
                float* c1 = acc[m2 * 4 + 2 * p + 1];
                mma16(c0, ah, &bhf[p][0]);
                mma16(c0, ah, &bmf[p][0]);
                mma16(c0, am, &bhf[p][0]);
                mma16(c1, ah, &bhf[p][2]);
                mma16(c1, ah, &bmf[p][2]);
                mma16(c1, am, &bhf[p][2]);
            }
        }
        __syncthreads();

        // ---- issue stage i+2 into buffer st ----
        const int nx = i + 2;
        if (nx < niter) {
            const int k0 = nx * BKC;
            cp16(dAh[st], gAh + k0, 16);
            cp16(dAm[st], gAm + k0, 16);
            cp16(dBh[st], gBh + k0, bsz);
            cp16(dBm[st], gBm + k0, bsz);
        }
        CP_COMMIT();
    }

    // ---- epilogue ----
#pragma unroll
    for (int m2 = 0; m2 < 4; m2++) {
        const int row0 = brow0 + wm + m2 * 16 + g;
#pragma unroll
        for (int nn = 0; nn < 4; nn++) {
            const int col = bcol0 + wn + nn * 8 + 2 * q;
            if (col < N) {
                const float* c = acc[m2 * 4 + nn];
                float o0 = c[0], o1 = c[1], o2 = c[2], o3 = c[3];
                if (mode == 1) {
                    o0 += bias[col]; o2 += bias[col];
                    o1 += bias[col + 1]; o3 += bias[col + 1];
                } else if (mode == 2) {
                    const float i0 = 2.f * bias[col], i1 = 2.f * bias[col + 1];
                    o0 += i0; o2 += i0; o1 += i1; o3 += i1;
                    o0 = (o0 > 20.f) ? o0 : log1pf(expf(o0));
                    o1 = (o1 > 20.f) ? o1 : log1pf(expf(o1));
                    o2 = (o2 > 20.f) ? o2 : log1pf(expf(o2));
                    o3 = (o3 > 20.f) ? o3 : log1pf(expf(o3));
                }
                *(float2*)&C[(size_t)row0 * ldc + col] = make_float2(o0, o1);
                *(float2*)&C[(size_t)(row0 + 8) * ldc + col] = make_float2(o2, o3);
                if (mode == 3 && col < DTRANK) {
                    __nv_bfloat16 h, m;
                    bsplit(o0, h, m);
                    auxh[(size_t)row0 * DTRANK + col] = h;
                    auxm[(size_t)row0 * DTRANK + col] = m;
                    bsplit(o1, h, m);
                    auxh[(size_t)row0 * DTRANK + col + 1] = h;
                    auxm[(size_t)row0 * DTRANK + col + 1] = m;
                    bsplit(o2, h, m);
                    auxh[(size_t)(row0 + 8) * DTRANK + col] = h;
                    auxm[(size_t)(row0 + 8) * DTRANK + col] = m;
                    bsplit(o3, h, m);
                    auxh[(size_t)(row0 + 8) * DTRANK + col + 1] = h;
                    auxm[(size_t)(row0 + 8) * DTRANK + col + 1] = m;
                }
            }
        }
    }
}

// ---------------- depthwise conv (k=4, SAME) + SiLU + bf16 split out --------
__global__ void conv_silu(const float* __restrict__ in, int istride,
                          const float* __restrict__ w, const float* __restrict__ bias,
                          float* __restrict__ outf,
                          __nv_bfloat16* __restrict__ oh, __nv_bfloat16* __restrict__ om,
                          int opitch, int ooff)
{
    const int idx = blockIdx.x * blockDim.x + threadIdx.x;
    const int row = idx >> 10;
    const int c   = idx & 1023;
    const int l   = row & (LEN - 1);

    float acc = bias[c];
#pragma unroll
    for (int j = 0; j < 4; j++) {
        const int ll = l - 1 + j;
        if ((unsigned)ll < (unsigned)LEN)
            acc = fmaf(w[j * DHALF + c], in[(size_t)(row - 1 + j) * istride + c], acc);
    }
    const float s = 1.f / (1.f + expf(-acc));
    const float v = acc * s;
    if (outf) outf[(size_t)row * DHALF + c] = v;
    __nv_bfloat16 h, m;
    bsplit(v, h, m);
    const size_t o = (size_t)row * opitch + ooff + c;
    oh[o] = h;
    om[o] = m;
}

// ---------------- selective scan: 4 threads per (b,d), bf16 split out -------
__global__ void scan_k(const float* __restrict__ u, const float* __restrict__ dl,
                       const float* __restrict__ xdbl, const float* __restrict__ Dv,
                       __nv_bfloat16* __restrict__ yh, __nv_bfloat16* __restrict__ ym)
{
    const int tid = blockIdx.x * blockDim.x + threadIdx.x;
    const int j  = tid & 3;
    const int bd = tid >> 2;
    const int d  = bd & (DHALF - 1);
    const int b  = bd >> 10;
    const float Dd = Dv[d];

    float h0 = 0.f, h1 = 0.f, h2 = 0.f, h3 = 0.f;
    size_t row = (size_t)b * LEN;
    for (int t = 0; t < LEN; t++, row++) {
        const float dval = dl[row * DHALF + d];
        const float uu   = u[row * DHALF + d];
        const float4 Bq = __ldg((const float4*)(xdbl + row * XDBL_W + 64) + j);
        const float4 Cq = __ldg((const float4*)(xdbl + row * XDBL_W + 80) + j);

        const float e1 = __expf(-dval);
        const float e2 = e1 * e1, e4 = e2 * e2, e8 = e4 * e4;
        float pj = (j & 1) ? e4 : 1.f;
        if (j & 2) pj *= e8;
        const float p0 = pj * e1;
        const float p1 = p0 * e1, p2 = p1 * e1, p3 = p2 * e1;
        const float xd = dval * uu;

        h0 = fmaf(p0, h0, xd * Bq.x);
        h1 = fmaf(p1, h1, xd * Bq.y);
        h2 = fmaf(p2, h2, xd * Bq.z);
        h3 = fmaf(p3, h3, xd * Bq.w);

        float cy = fmaf(h0, Cq.x, h1 * Cq.y) + fmaf(h2, Cq.z, h3 * Cq.w);
        cy += __shfl_xor_sync(0xffffffffu, cy, 1);
        cy += __shfl_xor_sync(0xffffffffu, cy, 2);
        if (j == 0) {
            const float yv = cy + uu * Dd;
            __nv_bfloat16 h, m;
            bsplit(yv, h, m);
            yh[row * DINNER + d] = h;
            ym[row * DINNER + d] = m;
        }
    }
}

// ---------------- launch --------------------------------------------------
extern "C" void kernel_launch(void* const* d_in, const int* in_sizes, int n_in,
                              void* d_out, int out_size)
{
    const float* x       = (const float*)d_in[0];
    const float* W_in    = (const float*)d_in[1];
    const float* conv_xw = (const float*)d_in[2];
    const float* conv_xb = (const float*)d_in[3];
    const float* conv_zw = (const float*)d_in[4];
    const float* conv_zb = (const float*)d_in[5];
    const float* W_xdbl  = (const float*)d_in[6];
    const float* W_dt    = (const float*)d_in[7];
    const float* inv_dt  = (const float*)d_in[8];
    const float* Dvec    = (const float*)d_in[9];
    const float* W_out   = (const float*)d_in[10];
    const float* b_out   = (const float*)d_in[11];
    float* out = (float*)d_out;

    float *p_xz, *p_u, *p_xdbl, *p_delta;
    cudaGetSymbolAddress((void**)&p_xz,    g_xz);
    cudaGetSymbolAddress((void**)&p_u,     g_u);
    cudaGetSymbolAddress((void**)&p_xdbl,  g_xdbl);
    cudaGetSymbolAddress((void**)&p_delta, g_delta);

    __nv_bfloat16 *xh, *xm, *uh, *um, *ych, *ycm, *dtlh, *dtlm;
    cudaGetSymbolAddress((void**)&xh,   g_xh);
    cudaGetSymbolAddress((void**)&xm,   g_xm);
    cudaGetSymbolAddress((void**)&uh,   g_uh);
    cudaGetSymbolAddress((void**)&um,   g_um);
    cudaGetSymbolAddress((void**)&ych,  g_ych);
    cudaGetSymbolAddress((void**)&ycm,  g_ycm);
    cudaGetSymbolAddress((void**)&dtlh, g_dtlh);
    cudaGetSymbolAddress((void**)&dtlm, g_dtlm);

    __nv_bfloat16 *w_in_h, *w_in_m, *w_xd_h, *w_xd_m, *w_dt_h, *w_dt_m, *w_out_h, *w_out_m;
    cudaGetSymbolAddress((void**)&w_in_h,  g_Win_h);
    cudaGetSymbolAddress((void**)&w_in_m,  g_Win_m);
    cudaGetSymbolAddress((void**)&w_xd_h,  g_Wxd_h);
    cudaGetSymbolAddress((void**)&w_xd_m,  g_Wxd_m);
    cudaGetSymbolAddress((void**)&w_dt_h,  g_Wdt_h);
    cudaGetSymbolAddress((void**)&w_dt_m,  g_Wdt_m);
    cudaGetSymbolAddress((void**)&w_out_h, g_Wout_h);
    cudaGetSymbolAddress((void**)&w_out_m, g_Wout_m);

    const dim3 tsb(32, 8);

    // 0) pre-split + transpose all weight matrices to [N][K] bf16 hi/mid
    tsplit<<<dim3(DINNER / 32, DMODEL / 32), tsb>>>(W_in,   w_in_h,  w_in_m,  DMODEL, DINNER);
    tsplit<<<dim3(XDBL_W / 32, DHALF / 32),  tsb>>>(W_xdbl, w_xd_h,  w_xd_m,  DHALF,  XDBL_W);
    tsplit<<<dim3(DHALF / 32, DTRANK / 32),  tsb>>>(W_dt,   w_dt_h,  w_dt_m,  DTRANK, DHALF);
    tsplit<<<dim3(DMODEL / 32, DINNER / 32), tsb>>>(W_out,  w_out_h, w_out_m, DINNER, DMODEL);

    // 0b) split x -> bf16 hi/mid
    asplit<<<(NROWS * DMODEL / 4) / 256, 256>>>(x, xh, xm);

    const int elemBlocks = (NROWS * DHALF) / 256;

    // 1) xz = x @ W_in   (8192 x 2048 x 1024)
    gemm_cs<<<dim3(DINNER / 128, NROWS / 128), 256>>>(
        xh, xm, w_in_h, w_in_m, p_xz, nullptr, nullptr, nullptr,
        DINNER, DMODEL, DINNER, 0);

    // 2) u = silu(conv(xs)) (fp32 + hi/mid);  3) ycat[:,1024:] = silu(conv(z)) (hi/mid)
    conv_silu<<<elemBlocks, 256>>>(p_xz,         DINNER, conv_xw, conv_xb,
                                   p_u, uh, um, DHALF, 0);
    conv_silu<<<elemBlocks, 256>>>(p_xz + DHALF, DINNER, conv_zw, conv_zb,
                                   nullptr, ych, ycm, DINNER, DHALF);

    // 4) x_dbl = u @ W_xdbl  (8192 x 96 x 1024); also emits dt_low hi/mid
    gemm_cs<<<dim3(1, NROWS / 128), 256>>>(
        uh, um, w_xd_h, w_xd_m, p_xdbl, nullptr, dtlh, dtlm,
        XDBL_W, DHALF, XDBL_W, 3);

    // 5) delta = softplus(dt_low @ W_dt + 2*inv_dt)   (8192 x 1024 x 64)
    gemm_cs<<<dim3(DHALF / 128, NROWS / 128), 256>>>(
        dtlh, dtlm, w_dt_h, w_dt_m, p_delta, inv_dt, nullptr, nullptr,
        DHALF, DTRANK, DHALF, 2);

    // 6) selective scan -> ycat[:, :1024] hi/mid
    scan_k<<<64, 256>>>(p_u, p_delta, p_xdbl, Dvec, ych, ycm);

    // 7) out = ycat @ W_out + b_out   (8192 x 1024 x 2048)
    gemm_cs<<<dim3(DMODEL / 128, NROWS / 128), 256>>>(
        ych, ycm, w_out_h, w_out_m, out, b_out, nullptr, nullptr,
        DMODEL, DINNER, DMODEL, 1);
}

// round 14
// speedup vs baseline: 1.2254x; 1.2254x over previous
#include <cuda_runtime.h>
#include <cuda_bf16.h>
#include <math.h>

#define BSZ    4
#define LEN    2048
#define DMODEL 1024
#define DINNER 2048
#define DHALF  1024
#define NROWS  (BSZ * LEN)   // 8192
#define XDBL_W 96
#define DTRANK 64

// ---------------- scratch (static device globals: allocation-free) ----------
__device__ __align__(16) float g_xz[(size_t)NROWS * DINNER];
__device__ __align__(16) float g_u[(size_t)NROWS * DHALF];
__device__ __align__(16) float g_ycat[(size_t)NROWS * DINNER];
__device__ __align__(16) float g_xdbl[(size_t)NROWS * XDBL_W];
__device__ __align__(16) float g_delta[(size_t)NROWS * DHALF];

// pre-split transposed weights: [N][K] bf16, hi + mid levels
__device__ __align__(16) __nv_bfloat16 g_Win_h[(size_t)DINNER * DMODEL];
__device__ __align__(16) __nv_bfloat16 g_Win_m[(size_t)DINNER * DMODEL];
__device__ __align__(16) __nv_bfloat16 g_Wxd_h[(size_t)XDBL_W * DHALF];
__device__ __align__(16) __nv_bfloat16 g_Wxd_m[(size_t)XDBL_W * DHALF];
__device__ __align__(16) __nv_bfloat16 g_Wdt_h[(size_t)DHALF * DTRANK];
__device__ __align__(16) __nv_bfloat16 g_Wdt_m[(size_t)DHALF * DTRANK];
__device__ __align__(16) __nv_bfloat16 g_Wout_h[(size_t)DMODEL * DINNER];
__device__ __align__(16) __nv_bfloat16 g_Wout_m[(size_t)DMODEL * DINNER];

// ---------------- weight transpose + bf16 hi/mid split ----------------------
__global__ void tsplit(const float* __restrict__ W, __nv_bfloat16* __restrict__ Th,
                       __nv_bfloat16* __restrict__ Tm, int K, int N)
{
    __shared__ float tile[32][33];
    const int n0 = blockIdx.x * 32, k0 = blockIdx.y * 32;
    const int tx = threadIdx.x, ty = threadIdx.y;   // 32 x 8
#pragma unroll
    for (int i = 0; i < 32; i += 8)
        tile[ty + i][tx] = W[(size_t)(k0 + ty + i) * N + n0 + tx];
    __syncthreads();
#pragma unroll
    for (int i = 0; i < 32; i += 8) {
        const float v = tile[tx][ty + i];
        const __nv_bfloat16 h = __float2bfloat16_rn(v);
        const __nv_bfloat16 m = __float2bfloat16_rn(v - __bfloat162float(h));
        const size_t o = (size_t)(n0 + ty + i) * K + k0 + tx;
        Th[o] = h;
        Tm[o] = m;
    }
}

// ================= bf16 3-term split GEMM, ldmatrix + double buffer =========
// C[M,N] = A[M,K] @ B[K,N], fp32 A, pre-split bf16 B^T ([N][K]).
// mode: 0 plain, 1 +bias, 2 softplus(acc + 2*bias).
// Block tile 128x128x16, 256 threads, 8 warps = 2(m) x 4(n), warp tile 64x32.
// Two smem stages at pitch 24 bf16 -> exactly 48 KB static smem, 1 sync/iter.

__device__ __forceinline__ void mma16(float* c, const unsigned* a, const unsigned* b) {
    asm volatile(
        "mma.sync.aligned.m16n8k16.row.col.f32.bf16.bf16.f32 "
        "{%0,%1,%2,%3}, {%4,%5,%6,%7}, {%8,%9}, {%0,%1,%2,%3};\n"
        : "+f"(c[0]), "+f"(c[1]), "+f"(c[2]), "+f"(c[3])
        : "r"(a[0]), "r"(a[1]), "r"(a[2]), "r"(a[3]), "r"(b[0]), "r"(b[1]));
}

__device__ __forceinline__ void ldsm4(unsigned* r, unsigned saddr) {
    asm volatile("ldmatrix.sync.aligned.m8n8.x4.shared.b16 {%0,%1,%2,%3}, [%4];"
        : "=r"(r[0]), "=r"(r[1]), "=r"(r[2]), "=r"(r[3]) : "r"(saddr));
}

__device__ __forceinline__ void split8(const float* v, unsigned* h4, unsigned* m4) {
#pragma unroll
    for (int i = 0; i < 4; i++) {
        const float x = v[2 * i], y = v[2 * i + 1];
        unsigned hp;
        asm("cvt.rn.satfinite.bf16x2.f32 %0, %1, %2;" : "=r"(hp) : "f"(y), "f"(x));
        const float hx = __uint_as_float(hp << 16);
        const float hy = __uint_as_float(hp & 0xffff0000u);
        const float rx = x - hx, ry = y - hy;
        unsigned mp;
        asm("cvt.rn.satfinite.bf16x2.f32 %0, %1, %2;" : "=r"(mp) : "f"(ry), "f"(rx));
        h4[i] = hp;
        m4[i] = mp;
    }
}

#define BM 128
#define BN 128
#define BK 16
#define PT 24    // bf16 pitch: LDSM phases cover all 32 banks, 16B-aligned rows

__global__ __launch_bounds__(256)
void gemm_bf3(const float* __restrict__ A,
              const __nv_bfloat16* __restrict__ Bh,
              const __nv_bfloat16* __restrict__ Bm,
              float* __restrict__ C, const float* __restrict__ bias,
              int N, int K, int lda, int ldc, int mode)
{
    __shared__ __align__(16) __nv_bfloat16 sAh[2][BM * PT];   // 6 KB each
    __shared__ __align__(16) __nv_bfloat16 sAm[2][BM * PT];
    __shared__ __align__(16) __nv_bfloat16 sBh[2][BN * PT];
    __shared__ __align__(16) __nv_bfloat16 sBm[2][BN * PT];   // total 48 KB

    const int tid  = threadIdx.x;
    const int lane = tid & 31;
    const int warp = tid >> 5;
    const int g = lane >> 2, q = lane & 3;
    const int wm = (warp & 1) * 64;
    const int wn = (warp >> 1) * 32;
    const int brow0 = blockIdx.y * BM;
    const int bcol0 = blockIdx.x * BN;

    const int ar = tid >> 1, akh = tid & 1;
    const float* Aptr = A + (size_t)(brow0 + ar) * lda + akh * 8;
    const int bn_g = bcol0 + ar;
    const bool bvalid = bn_g < N;
    const __nv_bfloat16* Bhp = Bh + (size_t)bn_g * K + akh * 8;
    const __nv_bfloat16* Bmp = Bm + (size_t)bn_g * K + akh * 8;
    const int a_st = ar * PT + akh * 8;

    // ldmatrix lane offsets (bytes, stage-relative)
    const int a_lr = (lane & 7) + ((lane >> 3) & 1) * 8;
    const int a_lc = (lane >> 4) * 8;
    const int b_lr = (lane & 7) + (lane >> 4) * 8;
    const int b_lc = ((lane >> 3) & 1) * 8;
    const unsigned aLo = ((wm + a_lr) * PT + a_lc) * 2;
    const unsigned bLo = ((wn + b_lr) * PT + b_lc) * 2;
    unsigned aOffh[2], aOffm[2], bOffh[2], bOffm[2];
#pragma unroll
    for (int s = 0; s < 2; s++) {
        aOffh[s] = (unsigned)__cvta_generic_to_shared(sAh[s]) + aLo;
        aOffm[s] = (unsigned)__cvta_generic_to_shared(sAm[s]) + aLo;
        bOffh[s] = (unsigned)__cvta_generic_to_shared(sBh[s]) + bLo;
        bOffm[s] = (unsigned)__cvta_generic_to_shared(sBm[s]) + bLo;
    }

    float acc[16][4];
#pragma unroll
    for (int i = 0; i < 16; i++)
#pragma unroll
        for (int j = 0; j < 4; j++) acc[i][j] = 0.f;

    const int niter = K / BK;

    // ---- prologue: chunk0 -> buf0; prefetch chunk1 into regs ----
    float4 a0 = *(const float4*)Aptr;
    float4 a1 = *(const float4*)(Aptr + 4);
    uint4 pbh = bvalid ? *(const uint4*)Bhp : make_uint4(0, 0, 0, 0);
    uint4 pbm = bvalid ? *(const uint4*)Bmp : make_uint4(0, 0, 0, 0);
    {
        float av[8] = {a0.x, a0.y, a0.z, a0.w, a1.x, a1.y, a1.z, a1.w};
        unsigned h4[4], m4[4];
        split8(av, h4, m4);
        *(uint4*)&sAh[0][a_st] = make_uint4(h4[0], h4[1], h4[2], h4[3]);
        *(uint4*)&sAm[0][a_st] = make_uint4(m4[0], m4[1], m4[2], m4[3]);
        *(uint4*)&sBh[0][a_st] = pbh;
        *(uint4*)&sBm[0][a_st] = pbm;
    }
    if (niter > 1) {
        a0 = *(const float4*)(Aptr + BK);
        a1 = *(const float4*)(Aptr + BK + 4);
        pbh = bvalid ? *(const uint4*)(Bhp + BK) : make_uint4(0, 0, 0, 0);
        pbm = bvalid ? *(const uint4*)(Bmp + BK) : make_uint4(0, 0, 0, 0);
    }
    __syncthreads();

    for (int i = 0; i < niter; i++) {
        const int st = i & 1;

        // ---- store chunk i+1 into the other buffer (from regs) ----
        if (i + 1 < niter) {
            float av[8] = {a0.x, a0.y, a0.z, a0.w, a1.x, a1.y, a1.z, a1.w};
            unsigned h4[4], m4[4];
            split8(av, h4, m4);
            *(uint4*)&sAh[st ^ 1][a_st] = make_uint4(h4[0], h4[1], h4[2], h4[3]);
            *(uint4*)&sAm[st ^ 1][a_st] = make_uint4(m4[0], m4[1], m4[2], m4[3]);
            *(uint4*)&sBh[st ^ 1][a_st] = pbh;
            *(uint4*)&sBm[st ^ 1][a_st] = pbm;
        }
        // ---- prefetch chunk i+2 into regs ----
        if (i + 2 < niter) {
            const int k0 = (i + 2) * BK;
            a0 = *(const float4*)(Aptr + k0);
            a1 = *(const float4*)(Aptr + k0 + 4);
            pbh = bvalid ? *(const uint4*)(Bhp + k0) : make_uint4(0, 0, 0, 0);
            pbm = bvalid ? *(const uint4*)(Bmp + k0) : make_uint4(0, 0, 0, 0);
        }

        // ---- compute buffer st ----
        unsigned bhf[2][4], bmf[2][4];
        ldsm4(bhf[0], bOffh[st]);
        ldsm4(bhf[1], bOffh[st] + 16 * PT * 2);
        ldsm4(bmf[0], bOffm[st]);
        ldsm4(bmf[1], bOffm[st] + 16 * PT * 2);
#pragma unroll
        for (int m2 = 0; m2 < 4; m2++) {
            unsigned ah[4], am[4];
            ldsm4(ah, aOffh[st] + m2 * (16 * PT * 2));
            ldsm4(am, aOffm[st] + m2 * (16 * PT * 2));
#pragma unroll
            for (int p = 0; p < 2; p++) {
                float* c0 = acc[m2 * 4 + 2 * p];
                float* c1 = acc[m2 * 4 + 2 * p + 1];
                mma16(c0, ah, &bhf[p][0]);
                mma16(c0, ah, &bmf[p][0]);
                mma16(c0, am, &bhf[p][0]);
                mma16(c1, ah, &bhf[p][2]);
                mma16(c1, ah, &bmf[p][2]);
                mma16(c1, am, &bhf[p][2]);
            }
        }
        __syncthreads();
    }

    // ---- epilogue ----
#pragma unroll
    for (int m2 = 0; m2 < 4; m2++) {
        const int row0 = brow0 + wm + m2 * 16 + g;
#pragma unroll
        for (int nn = 0; nn < 4; nn++) {
            const int col = bcol0 + wn + nn * 8 + 2 * q;
            if (col < N) {
                const float* c = acc[m2 * 4 + nn];
                float o0 = c[0], o1 = c[1], o2 = c[2], o3 = c[3];
                if (mode == 1) {
                    o0 += bias[col]; o2 += bias[col];
                    o1 += bias[col + 1]; o3 += bias[col + 1];
                } else if (mode == 2) {
                    const float i0 = 2.f * bias[col], i1 = 2.f * bias[col + 1];
                    o0 += i0; o2 += i0; o1 += i1; o3 += i1;
                    o0 = (o0 > 20.f) ? o0 : log1pf(expf(o0));
                    o1 = (o1 > 20.f) ? o1 : log1pf(expf(o1));
                    o2 = (o2 > 20.f) ? o2 : log1pf(expf(o2));
                    o3 = (o3 > 20.f) ? o3 : log1pf(expf(o3));
                }
                *(float2*)&C[(size_t)row0 * ldc + col] = make_float2(o0, o1);
                *(float2*)&C[(size_t)(row0 + 8) * ldc + col] = make_float2(o2, o3);
            }
        }
    }
}

// ---------------- depthwise conv (k=4, SAME: pad_l=1, pad_r=2) + SiLU -------
__global__ void conv_silu(const float* __restrict__ in, int istride,
                          const float* __restrict__ w, const float* __restrict__ bias,
                          float* __restrict__ out, int ostride)
{
    const int idx = blockIdx.x * blockDim.x + threadIdx.x;
    const int row = idx >> 10;
    const int c   = idx & 1023;
    const int l   = row & (LEN - 1);

    float acc = bias[c];
#pragma unroll
    for (int j = 0; j < 4; j++) {
        const int ll = l - 1 + j;
        if ((unsigned)ll < (unsigned)LEN)
            acc = fmaf(w[j * DHALF + c], in[(size_t)(row - 1 + j) * istride + c], acc);
    }
    const float s = 1.f / (1.f + expf(-acc));
    out[(size_t)row * ostride + c] = acc * s;
}

// ---------------- selective scan: 4 threads per (b,d), n-quad each ----------
__global__ void scan_k(const float* __restrict__ u, const float* __restrict__ dl,
                       const float* __restrict__ xdbl, const float* __restrict__ Dv,
                       float* __restrict__ y)
{
    const int tid = blockIdx.x * blockDim.x + threadIdx.x;
    const int j  = tid & 3;
    const int bd = tid >> 2;
    const int d  = bd & (DHALF - 1);
    const int b  = bd >> 10;
    const float Dd = Dv[d];

    float h0 = 0.f, h1 = 0.f, h2 = 0.f, h3 = 0.f;
    size_t row = (size_t)b * LEN;
    for (int t = 0; t < LEN; t++, row++) {
        const float dval = dl[row * DHALF + d];
        const float uu   = u[row * DHALF + d];
        const float4 Bq = __ldg((const float4*)(xdbl + row * XDBL_W + 64) + j);
        const float4 Cq = __ldg((const float4*)(xdbl + row * XDBL_W + 80) + j);

        const float e1 = __expf(-dval);
        const float e2 = e1 * e1, e4 = e2 * e2, e8 = e4 * e4;
        float pj = (j & 1) ? e4 : 1.f;
        if (j & 2) pj *= e8;
        const float p0 = pj * e1;
        const float p1 = p0 * e1, p2 = p1 * e1, p3 = p2 * e1;
        const float xd = dval * uu;

        h0 = fmaf(p0, h0, xd * Bq.x);
        h1 = fmaf(p1, h1, xd * Bq.y);
        h2 = fmaf(p2, h2, xd * Bq.z);
        h3 = fmaf(p3, h3, xd * Bq.w);

        float cy = fmaf(h0, Cq.x, h1 * Cq.y) + fmaf(h2, Cq.z, h3 * Cq.w);
        cy += __shfl_xor_sync(0xffffffffu, cy, 1);
        cy += __shfl_xor_sync(0xffffffffu, cy, 2);
        if (j == 0) y[row * DINNER + d] = cy + uu * Dd;
    }
}

// ---------------- launch --------------------------------------------------
extern "C" void kernel_launch(void* const* d_in, const int* in_sizes, int n_in,
                              void* d_out, int out_size)
{
    const float* x       = (const float*)d_in[0];
    const float* W_in    = (const float*)d_in[1];
    const float* conv_xw = (const float*)d_in[2];
    const float* conv_xb = (const float*)d_in[3];
    const float* conv_zw = (const float*)d_in[4];
    const float* conv_zb = (const float*)d_in[5];
    const float* W_xdbl  = (const float*)d_in[6];
    const float* W_dt    = (const float*)d_in[7];
    const float* inv_dt  = (const float*)d_in[8];
    const float* Dvec    = (const float*)d_in[9];
    const float* W_out   = (const float*)d_in[10];
    const float* b_out   = (const float*)d_in[11];
    float* out = (float*)d_out;

    float *p_xz, *p_u, *p_ycat, *p_xdbl, *p_delta;
    cudaGetSymbolAddress((void**)&p_xz,    g_xz);
    cudaGetSymbolAddress((void**)&p_u,     g_u);
    cudaGetSymbolAddress((void**)&p_ycat,  g_ycat);
    cudaGetSymbolAddress((void**)&p_xdbl,  g_xdbl);
    cudaGetSymbolAddress((void**)&p_delta, g_delta);

    __nv_bfloat16 *w_in_h, *w_in_m, *w_xd_h, *w_xd_m, *w_dt_h, *w_dt_m, *w_out_h, *w_out_m;
    cudaGetSymbolAddress((void**)&w_in_h,  g_Win_h);
    cudaGetSymbolAddress((void**)&w_in_m,  g_Win_m);
    cudaGetSymbolAddress((void**)&w_xd_h,  g_Wxd_h);
    cudaGetSymbolAddress((void**)&w_xd_m,  g_Wxd_m);
    cudaGetSymbolAddress((void**)&w_dt_h,  g_Wdt_h);
    cudaGetSymbolAddress((void**)&w_dt_m,  g_Wdt_m);
    cudaGetSymbolAddress((void**)&w_out_h, g_Wout_h);
    cudaGetSymbolAddress((void**)&w_out_m, g_Wout_m);

    const dim3 tsb(32, 8);

    // 0) pre-split + transpose all weight matrices to [N][K] bf16 hi/mid
    tsplit<<<dim3(DINNER / 32, DMODEL / 32), tsb>>>(W_in,   w_in_h,  w_in_m,  DMODEL, DINNER);
    tsplit<<<dim3(XDBL_W / 32, DHALF / 32),  tsb>>>(W_xdbl, w_xd_h,  w_xd_m,  DHALF,  XDBL_W);
    tsplit<<<dim3(DHALF / 32, DTRANK / 32),  tsb>>>(W_dt,   w_dt_h,  w_dt_m,  DTRANK, DHALF);
    tsplit<<<dim3(DMODEL / 32, DINNER / 32), tsb>>>(W_out,  w_out_h, w_out_m, DINNER, DMODEL);

    const int elemBlocks = (NROWS * DHALF) / 256;

    // 1) xz = x @ W_in   (8192 x 2048 x 1024)
    gemm_bf3<<<dim3(DINNER / BN, NROWS / BM), 256>>>(
        x, w_in_h, w_in_m, p_xz, nullptr, DINNER, DMODEL, DMODEL, DINNER, 0);

    // 2) u = silu(conv(xs));  3) ycat[:,1024:] = silu(conv(z))
    conv_silu<<<elemBlocks, 256>>>(p_xz,         DINNER, conv_xw, conv_xb, p_u,            DHALF);
    conv_silu<<<elemBlocks, 256>>>(p_xz + DHALF, DINNER, conv_zw, conv_zb, p_ycat + DHALF, DINNER);

    // 4) x_dbl = u @ W_xdbl   (8192 x 96 x 1024)
    gemm_bf3<<<dim3(1, NROWS / BM), 256>>>(
        p_u, w_xd_h, w_xd_m, p_xdbl, nullptr, XDBL_W, DHALF, DHALF, XDBL_W, 0);

    // 5) delta = softplus(dt_low @ W_dt + 2*inv_dt)   (fused epilogue)
    gemm_bf3<<<dim3(DHALF / BN, NROWS / BM), 256>>>(
        p_xdbl, w_dt_h, w_dt_m, p_delta, inv_dt, DHALF, DTRANK, XDBL_W, DHALF, 2);

    // 6) selective scan -> ycat[:, :1024]
    scan_k<<<64, 256>>>(p_u, p_delta, p_xdbl, Dvec, p_ycat);

    // 7) out = ycat @ W_out + b_out   (8192 x 1024 x 2048)
    gemm_bf3<<<dim3(DMODEL / BN, NROWS / BM), 256>>>(
        p_ycat, w_out_h, w_out_m, out, b_out, DMODEL, DINNER, DINNER, DMODEL, 1);
}

// round 15
// speedup vs baseline: 1.3554x; 1.1061x over previous
#include <cuda_runtime.h>
#include <cuda_fp16.h>
#include <math.h>

#define BSZ    4
#define LEN    2048
#define DMODEL 1024
#define DINNER 2048
#define DHALF  1024
#define NROWS  (BSZ * LEN)   // 8192
#define XDBL_W 96
#define DTRANK 64

// ---------------- scratch (static device globals: allocation-free) ----------
__device__ __align__(16) float g_xz[(size_t)NROWS * DINNER];
__device__ __align__(16) float g_u[(size_t)NROWS * DHALF];
__device__ __align__(16) float g_ycat[(size_t)NROWS * DINNER];
__device__ __align__(16) float g_xdbl[(size_t)NROWS * XDBL_W];
__device__ __align__(16) float g_delta[(size_t)NROWS * DHALF];

// pre-split transposed weights: [N][K] fp16, hi + mid levels
__device__ __align__(16) __half g_Win_h[(size_t)DINNER * DMODEL];
__device__ __align__(16) __half g_Win_m[(size_t)DINNER * DMODEL];
__device__ __align__(16) __half g_Wxd_h[(size_t)XDBL_W * DHALF];
__device__ __align__(16) __half g_Wxd_m[(size_t)XDBL_W * DHALF];
__device__ __align__(16) __half g_Wdt_h[(size_t)DHALF * DTRANK];
__device__ __align__(16) __half g_Wdt_m[(size_t)DHALF * DTRANK];
__device__ __align__(16) __half g_Wout_h[(size_t)DMODEL * DINNER];
__device__ __align__(16) __half g_Wout_m[(size_t)DMODEL * DINNER];

// ---------------- weight transpose + fp16 hi/mid split -----------------------
__global__ void tsplit(const float* __restrict__ W, __half* __restrict__ Th,
                       __half* __restrict__ Tm, int K, int N)
{
    __shared__ float tile[32][33];
    const int n0 = blockIdx.x * 32, k0 = blockIdx.y * 32;
    const int tx = threadIdx.x, ty = threadIdx.y;   // 32 x 8
#pragma unroll
    for (int i = 0; i < 32; i += 8)
        tile[ty + i][tx] = W[(size_t)(k0 + ty + i) * N + n0 + tx];
    __syncthreads();
#pragma unroll
    for (int i = 0; i < 32; i += 8) {
        const float v = tile[tx][ty + i];
        const __half h = __float2half_rn(v);
        const __half m = __float2half_rn(v - __half2float(h));
        const size_t o = (size_t)(n0 + ty + i) * K + k0 + tx;
        Th[o] = h;
        Tm[o] = m;
    }
}

// ========== fp16 2-term split GEMM: C = A*(Bh+Bm), A single fp16 ============
// C[M,N] = A[M,K] @ B[K,N], fp32 A converted in-kernel, pre-split fp16 B^T.
// mode: 0 plain, 1 +bias, 2 softplus(acc + 2*bias).
// Block tile 128x128x16, 256 threads, 8 warps = 2(m) x 4(n), warp tile 64x32.
// Two smem stages, pitch 24 fp16 -> 36 KB static smem.

__device__ __forceinline__ void mma16(float* c, const unsigned* a, const unsigned* b) {
    asm volatile(
        "mma.sync.aligned.m16n8k16.row.col.f32.f16.f16.f32 "
        "{%0,%1,%2,%3}, {%4,%5,%6,%7}, {%8,%9}, {%0,%1,%2,%3};\n"
        : "+f"(c[0]), "+f"(c[1]), "+f"(c[2]), "+f"(c[3])
        : "r"(a[0]), "r"(a[1]), "r"(a[2]), "r"(a[3]), "r"(b[0]), "r"(b[1]));
}

__device__ __forceinline__ void ldsm4(unsigned* r, unsigned saddr) {
    asm volatile("ldmatrix.sync.aligned.m8n8.x4.shared.b16 {%0,%1,%2,%3}, [%4];"
        : "=r"(r[0]), "=r"(r[1]), "=r"(r[2]), "=r"(r[3]) : "r"(saddr));
}

__device__ __forceinline__ void cvt8(const float* v, unsigned* h4) {
#pragma unroll
    for (int i = 0; i < 4; i++) {
        asm("cvt.rn.satfinite.f16x2.f32 %0, %1, %2;"
            : "=r"(h4[i]) : "f"(v[2 * i + 1]), "f"(v[2 * i]));
    }
}

#define BM 128
#define BN 128
#define BK 16
#define PT 24    // fp16 pitch: LDSM phases cover all 32 banks, 16B-aligned rows

__global__ __launch_bounds__(256)
void gemm_f2(const float* __restrict__ A,
             const __half* __restrict__ Bh,
             const __half* __restrict__ Bm,
             float* __restrict__ C, const float* __restrict__ bias,
             int N, int K, int lda, int ldc, int mode)
{
    __shared__ __align__(16) __half sA[2][BM * PT];    // 6 KB each
    __shared__ __align__(16) __half sBh[2][BN * PT];
    __shared__ __align__(16) __half sBm[2][BN * PT];   // total 36 KB

    const int tid  = threadIdx.x;
    const int lane = tid & 31;
    const int warp = tid >> 5;
    const int g = lane >> 2, q = lane & 3;
    const int wm = (warp & 1) * 64;
    const int wn = (warp >> 1) * 32;
    const int brow0 = blockIdx.y * BM;
    const int bcol0 = blockIdx.x * BN;

    const int ar = tid >> 1, akh = tid & 1;
    const float* Aptr = A + (size_t)(brow0 + ar) * lda + akh * 8;
    const int bn_g = bcol0 + ar;
    const bool bvalid = bn_g < N;
    const __half* Bhp = Bh + (size_t)bn_g * K + akh * 8;
    const __half* Bmp = Bm + (size_t)bn_g * K + akh * 8;
    const int a_st = ar * PT + akh * 8;

    // ldmatrix lane offsets (bytes, stage-relative)
    const int a_lr = (lane & 7) + ((lane >> 3) & 1) * 8;
    const int a_lc = (lane >> 4) * 8;
    const int b_lr = (lane & 7) + (lane >> 4) * 8;
    const int b_lc = ((lane >> 3) & 1) * 8;
    const unsigned aLo = ((wm + a_lr) * PT + a_lc) * 2;
    const unsigned bLo = ((wn + b_lr) * PT + b_lc) * 2;
    unsigned aOff[2], bOffh[2], bOffm[2];
#pragma unroll
    for (int s = 0; s < 2; s++) {
        aOff[s]  = (unsigned)__cvta_generic_to_shared(sA[s])  + aLo;
        bOffh[s] = (unsigned)__cvta_generic_to_shared(sBh[s]) + bLo;
        bOffm[s] = (unsigned)__cvta_generic_to_shared(sBm[s]) + bLo;
    }

    float acc[16][4];
#pragma unroll
    for (int i = 0; i < 16; i++)
#pragma unroll
        for (int j = 0; j < 4; j++) acc[i][j] = 0.f;

    const int niter = K / BK;

    // ---- prologue: chunk0 -> buf0; prefetch chunk1 into regs ----
    float4 a0 = *(const float4*)Aptr;
    float4 a1 = *(const float4*)(Aptr + 4);
    uint4 pbh = bvalid ? *(const uint4*)Bhp : make_uint4(0, 0, 0, 0);
    uint4 pbm = bvalid ? *(const uint4*)Bmp : make_uint4(0, 0, 0, 0);
    {
        float av[8] = {a0.x, a0.y, a0.z, a0.w, a1.x, a1.y, a1.z, a1.w};
        unsigned h4[4];
        cvt8(av, h4);
        *(uint4*)&sA[0][a_st]  = make_uint4(h4[0], h4[1], h4[2], h4[3]);
        *(uint4*)&sBh[0][a_st] = pbh;
        *(uint4*)&sBm[0][a_st] = pbm;
    }
    if (niter > 1) {
        a0 = *(const float4*)(Aptr + BK);
        a1 = *(const float4*)(Aptr + BK + 4);
        pbh = bvalid ? *(const uint4*)(Bhp + BK) : make_uint4(0, 0, 0, 0);
        pbm = bvalid ? *(const uint4*)(Bmp + BK) : make_uint4(0, 0, 0, 0);
    }
    __syncthreads();

    for (int i = 0; i < niter; i++) {
        const int st = i & 1;

        // ---- store chunk i+1 into the other buffer (from regs) ----
        if (i + 1 < niter) {
            float av[8] = {a0.x, a0.y, a0.z, a0.w, a1.x, a1.y, a1.z, a1.w};
            unsigned h4[4];
            cvt8(av, h4);
            *(uint4*)&sA[st ^ 1][a_st]  = make_uint4(h4[0], h4[1], h4[2], h4[3]);
            *(uint4*)&sBh[st ^ 1][a_st] = pbh;
            *(uint4*)&sBm[st ^ 1][a_st] = pbm;
        }
        // ---- prefetch chunk i+2 into regs ----
        if (i + 2 < niter) {
            const int k0 = (i + 2) * BK;
            a0 = *(const float4*)(Aptr + k0);
            a1 = *(const float4*)(Aptr + k0 + 4);
            pbh = bvalid ? *(const uint4*)(Bhp + k0) : make_uint4(0, 0, 0, 0);
            pbm = bvalid ? *(const uint4*)(Bmp + k0) : make_uint4(0, 0, 0, 0);
        }

        // ---- compute buffer st: 2 terms (A*Bh + A*Bm) ----
        unsigned bhf[2][4], bmf[2][4];
        ldsm4(bhf[0], bOffh[st]);
        ldsm4(bhf[1], bOffh[st] + 16 * PT * 2);
        ldsm4(bmf[0], bOffm[st]);
        ldsm4(bmf[1], bOffm[st] + 16 * PT * 2);
#pragma unroll
        for (int m2 = 0; m2 < 4; m2++) {
            unsigned ah[4];
            ldsm4(ah, aOff[st] + m2 * (16 * PT * 2));
#pragma unroll
            for (int p = 0; p < 2; p++) {
                float* c0 = acc[m2 * 4 + 2 * p];
                float* c1 = acc[m2 * 4 + 2 * p + 1];
                mma16(c0, ah, &bhf[p][0]);
                mma16(c0, ah, &bmf[p][0]);
                mma16(c1, ah, &bhf[p][2]);
                mma16(c1, ah, &bmf[p][2]);
            }
        }
        __syncthreads();
    }

    // ---- epilogue ----
#pragma unroll
    for (int m2 = 0; m2 < 4; m2++) {
        const int row0 = brow0 + wm + m2 * 16 + g;
#pragma unroll
        for (int nn = 0; nn < 4; nn++) {
            const int col = bcol0 + wn + nn * 8 + 2 * q;
            if (col < N) {
                const float* c = acc[m2 * 4 + nn];
                float o0 = c[0], o1 = c[1], o2 = c[2], o3 = c[3];
                if (mode == 1) {
                    o0 += bias[col]; o2 += bias[col];
                    o1 += bias[col + 1]; o3 += bias[col + 1];
                } else if (mode == 2) {
                    const float i0 = 2.f * bias[col], i1 = 2.f * bias[col + 1];
                    o0 += i0; o2 += i0; o1 += i1; o3 += i1;
                    o0 = (o0 > 20.f) ? o0 : log1pf(expf(o0));
                    o1 = (o1 > 20.f) ? o1 : log1pf(expf(o1));
                    o2 = (o2 > 20.f) ? o2 : log1pf(expf(o2));
                    o3 = (o3 > 20.f) ? o3 : log1pf(expf(o3));
                }
                *(float2*)&C[(size_t)row0 * ldc + col] = make_float2(o0, o1);
                *(float2*)&C[(size_t)(row0 + 8) * ldc + col] = make_float2(o2, o3);
            }
        }
    }
}

// ---------------- depthwise conv (k=4, SAME: pad_l=1, pad_r=2) + SiLU -------
__global__ void conv_silu(const float* __restrict__ in, int istride,
                          const float* __restrict__ w, const float* __restrict__ bias,
                          float* __restrict__ out, int ostride)
{
    const int idx = blockIdx.x * blockDim.x + threadIdx.x;
    const int row = idx >> 10;
    const int c   = idx & 1023;
    const int l   = row & (LEN - 1);

    float acc = bias[c];
#pragma unroll
    for (int j = 0; j < 4; j++) {
        const int ll = l - 1 + j;
        if ((unsigned)ll < (unsigned)LEN)
            acc = fmaf(w[j * DHALF + c], in[(size_t)(row - 1 + j) * istride + c], acc);
    }
    const float s = 1.f / (1.f + expf(-acc));
    out[(size_t)row * ostride + c] = acc * s;
}

// ---------------- selective scan: 4 threads per (b,d), n-quad each ----------
__global__ void scan_k(const float* __restrict__ u, const float* __restrict__ dl,
                       const float* __restrict__ xdbl, const float* __restrict__ Dv,
                       float* __restrict__ y)
{
    const int tid = blockIdx.x * blockDim.x + threadIdx.x;
    const int j  = tid & 3;
    const int bd = tid >> 2;
    const int d  = bd & (DHALF - 1);
    const int b  = bd >> 10;
    const float Dd = Dv[d];

    float h0 = 0.f, h1 = 0.f, h2 = 0.f, h3 = 0.f;
    size_t row = (size_t)b * LEN;
    for (int t = 0; t < LEN; t++, row++) {
        const float dval = dl[row * DHALF + d];
        const float uu   = u[row * DHALF + d];
        const float4 Bq = __ldg((const float4*)(xdbl + row * XDBL_W + 64) + j);
        const float4 Cq = __ldg((const float4*)(xdbl + row * XDBL_W + 80) + j);

        const float e1 = __expf(-dval);
        const float e2 = e1 * e1, e4 = e2 * e2, e8 = e4 * e4;
        float pj = (j & 1) ? e4 : 1.f;
        if (j & 2) pj *= e8;
        const float p0 = pj * e1;
        const float p1 = p0 * e1, p2 = p1 * e1, p3 = p2 * e1;
        const float xd = dval * uu;

        h0 = fmaf(p0, h0, xd * Bq.x);
        h1 = fmaf(p1, h1, xd * Bq.y);
        h2 = fmaf(p2, h2, xd * Bq.z);
        h3 = fmaf(p3, h3, xd * Bq.w);

        float cy = fmaf(h0, Cq.x, h1 * Cq.y) + fmaf(h2, Cq.z, h3 * Cq.w);
        cy += __shfl_xor_sync(0xffffffffu, cy, 1);
        cy += __shfl_xor_sync(0xffffffffu, cy, 2);
        if (j == 0) y[row * DINNER + d] = cy + uu * Dd;
    }
}

// ---------------- launch --------------------------------------------------
extern "C" void kernel_launch(void* const* d_in, const int* in_sizes, int n_in,
                              void* d_out, int out_size)
{
    const float* x       = (const float*)d_in[0];
    const float* W_in    = (const float*)d_in[1];
    const float* conv_xw = (const float*)d_in[2];
    const float* conv_xb = (const float*)d_in[3];
    const float* conv_zw = (const float*)d_in[4];
    const float* conv_zb = (const float*)d_in[5];
    const float* W_xdbl  = (const float*)d_in[6];
    const float* W_dt    = (const float*)d_in[7];
    const float* inv_dt  = (const float*)d_in[8];
    const float* Dvec    = (const float*)d_in[9];
    const float* W_out   = (const float*)d_in[10];
    const float* b_out   = (const float*)d_in[11];
    float* out = (float*)d_out;

    float *p_xz, *p_u, *p_ycat, *p_xdbl, *p_delta;
    cudaGetSymbolAddress((void**)&p_xz,    g_xz);
    cudaGetSymbolAddress((void**)&p_u,     g_u);
    cudaGetSymbolAddress((void**)&p_ycat,  g_ycat);
    cudaGetSymbolAddress((void**)&p_xdbl,  g_xdbl);
    cudaGetSymbolAddress((void**)&p_delta, g_delta);

    __half *w_in_h, *w_in_m, *w_xd_h, *w_xd_m, *w_dt_h, *w_dt_m, *w_out_h, *w_out_m;
    cudaGetSymbolAddress((void**)&w_in_h,  g_Win_h);
    cudaGetSymbolAddress((void**)&w_in_m,  g_Win_m);
    cudaGetSymbolAddress((void**)&w_xd_h,  g_Wxd_h);
    cudaGetSymbolAddress((void**)&w_xd_m,  g_Wxd_m);
    cudaGetSymbolAddress((void**)&w_dt_h,  g_Wdt_h);
    cudaGetSymbolAddress((void**)&w_dt_m,  g_Wdt_m);
    cudaGetSymbolAddress((void**)&w_out_h, g_Wout_h);
    cudaGetSymbolAddress((void**)&w_out_m, g_Wout_m);

    const dim3 tsb(32, 8);

    // 0) pre-split + transpose all weight matrices to [N][K] fp16 hi/mid
    tsplit<<<dim3(DINNER / 32, DMODEL / 32), tsb>>>(W_in,   w_in_h,  w_in_m,  DMODEL, DINNER);
    tsplit<<<dim3(XDBL_W / 32, DHALF / 32),  tsb>>>(W_xdbl, w_xd_h,  w_xd_m,  DHALF,  XDBL_W);
    tsplit<<<dim3(DHALF / 32, DTRANK / 32),  tsb>>>(W_dt,   w_dt_h,  w_dt_m,  DTRANK, DHALF);
    tsplit<<<dim3(DMODEL / 32, DINNER / 32), tsb>>>(W_out,  w_out_h, w_out_m, DINNER, DMODEL);

    const int elemBlocks = (NROWS * DHALF) / 256;

    // 1) xz = x @ W_in   (8192 x 2048 x 1024)
    gemm_f2<<<dim3(DINNER / BN, NROWS / BM), 256>>>(
        x, w_in_h, w_in_m, p_xz, nullptr, DINNER, DMODEL, DMODEL, DINNER, 0);

    // 2) u = silu(conv(xs));  3) ycat[:,1024:] = silu(conv(z))
    conv_silu<<<elemBlocks, 256>>>(p_xz,         DINNER, conv_xw, conv_xb, p_u,            DHALF);
    conv_silu<<<elemBlocks, 256>>>(p_xz + DHALF, DINNER, conv_zw, conv_zb, p_ycat + DHALF, DINNER);

    // 4) x_dbl = u @ W_xdbl   (8192 x 96 x 1024)
    gemm_f2<<<dim3(1, NROWS / BM), 256>>>(
        p_u, w_xd_h, w_xd_m, p_xdbl, nullptr, XDBL_W, DHALF, DHALF, XDBL_W, 0);

    // 5) delta = softplus(dt_low @ W_dt + 2*inv_dt)   (fused epilogue)
    gemm_f2<<<dim3(DHALF / BN, NROWS / BM), 256>>>(
        p_xdbl, w_dt_h, w_dt_m, p_delta, inv_dt, DHALF, DTRANK, XDBL_W, DHALF, 2);

    // 6) selective scan -> ycat[:, :1024]
    scan_k<<<64, 256>>>(p_u, p_delta, p_xdbl, Dvec, p_ycat);

    // 7) out = ycat @ W_out + b_out   (8192 x 1024 x 2048)
    gemm_f2<<<dim3(DMODEL / BN, NROWS / BM), 256>>>(
        p_ycat, w_out_h, w_out_m, out, b_out, DMODEL, DINNER, DINNER, DMODEL, 1);
}

// round 16
// speedup vs baseline: 1.5843x; 1.1688x over previous
#include <cuda_runtime.h>
#include <cuda_fp16.h>
#include <math.h>

#define BSZ    4
#define LEN    2048
#define DMODEL 1024
#define DINNER 2048
#define DHALF  1024
#define NROWS  (BSZ * LEN)   // 8192
#define XDBL_W 96
#define DTRANK 64

// ---------------- scratch (static device globals: allocation-free) ----------
__device__ __align__(16) float g_xz[(size_t)NROWS * DINNER];
__device__ __align__(16) float g_u[(size_t)NROWS * DHALF];
__device__ __align__(16) float g_ycat[(size_t)NROWS * DINNER];
__device__ __align__(16) float g_xdbl[(size_t)NROWS * XDBL_W];
__device__ __align__(16) float g_delta[(size_t)NROWS * DHALF];

// pre-split transposed weights: [N][K] fp16, hi + mid levels
__device__ __align__(16) __half g_Win_h[(size_t)DINNER * DMODEL];
__device__ __align__(16) __half g_Win_m[(size_t)DINNER * DMODEL];
__device__ __align__(16) __half g_Wxd_h[(size_t)XDBL_W * DHALF];
__device__ __align__(16) __half g_Wxd_m[(size_t)XDBL_W * DHALF];
__device__ __align__(16) __half g_Wdt_h[(size_t)DHALF * DTRANK];
__device__ __align__(16) __half g_Wdt_m[(size_t)DHALF * DTRANK];
__device__ __align__(16) __half g_Wout_h[(size_t)DMODEL * DINNER];
__device__ __align__(16) __half g_Wout_m[(size_t)DMODEL * DINNER];

// ---------------- weight transpose + fp16 hi/mid split -----------------------
__global__ void tsplit(const float* __restrict__ W, __half* __restrict__ Th,
                       __half* __restrict__ Tm, int K, int N)
{
    __shared__ float tile[32][33];
    const int n0 = blockIdx.x * 32, k0 = blockIdx.y * 32;
    const int tx = threadIdx.x, ty = threadIdx.y;   // 32 x 8
#pragma unroll
    for (int i = 0; i < 32; i += 8)
        tile[ty + i][tx] = W[(size_t)(k0 + ty + i) * N + n0 + tx];
    __syncthreads();
#pragma unroll
    for (int i = 0; i < 32; i += 8) {
        const float v = tile[tx][ty + i];
        const __half h = __float2half_rn(v);
        const __half m = __float2half_rn(v - __half2float(h));
        const size_t o = (size_t)(n0 + ty + i) * K + k0 + tx;
        Th[o] = h;
        Tm[o] = m;
    }
}

// ========== fp16 split GEMM: C = A*(Bh[+Bm]), A single fp16 =================
// TERMS=1: C = A*Bh (plain fp16 weights). TERMS=2: C = A*Bh + A*Bm.
// C[M,N] = A[M,K] @ B[K,N], fp32 A converted in-kernel, pre-split fp16 B^T.
// mode: 0 plain, 1 +bias, 2 softplus(acc + 2*bias).
// Block tile 128x128x16, 256 threads, 8 warps = 2(m) x 4(n), warp tile 64x32.
// Two smem stages, pitch 24 fp16.

__device__ __forceinline__ void mma16(float* c, const unsigned* a, const unsigned* b) {
    asm volatile(
        "mma.sync.aligned.m16n8k16.row.col.f32.f16.f16.f32 "
        "{%0,%1,%2,%3}, {%4,%5,%6,%7}, {%8,%9}, {%0,%1,%2,%3};\n"
        : "+f"(c[0]), "+f"(c[1]), "+f"(c[2]), "+f"(c[3])
        : "r"(a[0]), "r"(a[1]), "r"(a[2]), "r"(a[3]), "r"(b[0]), "r"(b[1]));
}

__device__ __forceinline__ void ldsm4(unsigned* r, unsigned saddr) {
    asm volatile("ldmatrix.sync.aligned.m8n8.x4.shared.b16 {%0,%1,%2,%3}, [%4];"
        : "=r"(r[0]), "=r"(r[1]), "=r"(r[2]), "=r"(r[3]) : "r"(saddr));
}

__device__ __forceinline__ void cvt8(const float* v, unsigned* h4) {
#pragma unroll
    for (int i = 0; i < 4; i++) {
        asm("cvt.rn.satfinite.f16x2.f32 %0, %1, %2;"
            : "=r"(h4[i]) : "f"(v[2 * i + 1]), "f"(v[2 * i]));
    }
}

#define BM 128
#define BN 128
#define BK 16
#define PT 24    // fp16 pitch: LDSM phases cover all 32 banks, 16B-aligned rows

template <int TERMS>
__global__ __launch_bounds__(256)
void gemm_f2(const float* __restrict__ A,
             const __half* __restrict__ Bh,
             const __half* __restrict__ Bm,
             float* __restrict__ C, const float* __restrict__ bias,
             int N, int K, int lda, int ldc, int mode)
{
    __shared__ __align__(16) __half sA[2][BM * PT];    // 6 KB each
    __shared__ __align__(16) __half sBh[2][BN * PT];
    __shared__ __align__(16) __half sBm[TERMS == 2 ? 2 : 1][BN * PT];

    const int tid  = threadIdx.x;
    const int lane = tid & 31;
    const int warp = tid >> 5;
    const int g = lane >> 2, q = lane & 3;
    const int wm = (warp & 1) * 64;
    const int wn = (warp >> 1) * 32;
    const int brow0 = blockIdx.y * BM;
    const int bcol0 = blockIdx.x * BN;

    const int ar = tid >> 1, akh = tid & 1;
    const float* Aptr = A + (size_t)(brow0 + ar) * lda + akh * 8;
    const int bn_g = bcol0 + ar;
    const bool bvalid = bn_g < N;
    const __half* Bhp = Bh + (size_t)bn_g * K + akh * 8;
    const __half* Bmp = Bm + (size_t)bn_g * K + akh * 8;
    const int a_st = ar * PT + akh * 8;

    // ldmatrix lane offsets (bytes, stage-relative)
    const int a_lr = (lane & 7) + ((lane >> 3) & 1) * 8;
    const int a_lc = (lane >> 4) * 8;
    const int b_lr = (lane & 7) + (lane >> 4) * 8;
    const int b_lc = ((lane >> 3) & 1) * 8;
    const unsigned aLo = ((wm + a_lr) * PT + a_lc) * 2;
    const unsigned bLo = ((wn + b_lr) * PT + b_lc) * 2;
    unsigned aOff[2], bOffh[2], bOffm[2];
#pragma unroll
    for (int s = 0; s < 2; s++) {
        aOff[s]  = (unsigned)__cvta_generic_to_shared(sA[s])  + aLo;
        bOffh[s] = (unsigned)__cvta_generic_to_shared(sBh[s]) + bLo;
        bOffm[s] = (unsigned)__cvta_generic_to_shared(sBm[TERMS == 2 ? s : 0]) + bLo;
    }

    float acc[16][4];
#pragma unroll
    for (int i = 0; i < 16; i++)
#pragma unroll
        for (int j = 0; j < 4; j++) acc[i][j] = 0.f;

    const int niter = K / BK;

    // ---- prologue: chunk0 -> buf0; prefetch chunk1 into regs ----
    float4 a0 = *(const float4*)Aptr;
    float4 a1 = *(const float4*)(Aptr + 4);
    uint4 pbh = bvalid ? *(const uint4*)Bhp : make_uint4(0, 0, 0, 0);
    uint4 pbm = make_uint4(0, 0, 0, 0);
    if (TERMS == 2 && bvalid) pbm = *(const uint4*)Bmp;
    {
        float av[8] = {a0.x, a0.y, a0.z, a0.w, a1.x, a1.y, a1.z, a1.w};
        unsigned h4[4];
        cvt8(av, h4);
        *(uint4*)&sA[0][a_st]  = make_uint4(h4[0], h4[1], h4[2], h4[3]);
        *(uint4*)&sBh[0][a_st] = pbh;
        if (TERMS == 2) *(uint4*)&sBm[0][a_st] = pbm;
    }
    if (niter > 1) {
        a0 = *(const float4*)(Aptr + BK);
        a1 = *(const float4*)(Aptr + BK + 4);
        pbh = bvalid ? *(const uint4*)(Bhp + BK) : make_uint4(0, 0, 0, 0);
        if (TERMS == 2)
            pbm = bvalid ? *(const uint4*)(Bmp + BK) : make_uint4(0, 0, 0, 0);
    }
    __syncthreads();

    for (int i = 0; i < niter; i++) {
        const int st = i & 1;

        // ---- store chunk i+1 into the other buffer (from regs) ----
        if (i + 1 < niter) {
            float av[8] = {a0.x, a0.y, a0.z, a0.w, a1.x, a1.y, a1.z, a1.w};
            unsigned h4[4];
            cvt8(av, h4);
            *(uint4*)&sA[st ^ 1][a_st]  = make_uint4(h4[0], h4[1], h4[2], h4[3]);
            *(uint4*)&sBh[st ^ 1][a_st] = pbh;
            if (TERMS == 2) *(uint4*)&sBm[st ^ 1][a_st] = pbm;
        }
        // ---- prefetch chunk i+2 into regs ----
        if (i + 2 < niter) {
            const int k0 = (i + 2) * BK;
            a0 = *(const float4*)(Aptr + k0);
            a1 = *(const float4*)(Aptr + k0 + 4);
            pbh = bvalid ? *(const uint4*)(Bhp + k0) : make_uint4(0, 0, 0, 0);
            if (TERMS == 2)
                pbm = bvalid ? *(const uint4*)(Bmp + k0) : make_uint4(0, 0, 0, 0);
        }

        // ---- compute buffer st ----
        unsigned bhf[2][4], bmf[2][4];
        ldsm4(bhf[0], bOffh[st]);
        ldsm4(bhf[1], bOffh[st] + 16 * PT * 2);
        if (TERMS == 2) {
            ldsm4(bmf[0], bOffm[st]);
            ldsm4(bmf[1], bOffm[st] + 16 * PT * 2);
        }
#pragma unroll
        for (int m2 = 0; m2 < 4; m2++) {
            unsigned ah[4];
            ldsm4(ah, aOff[st] + m2 * (16 * PT * 2));
#pragma unroll
            for (int p = 0; p < 2; p++) {
                float* c0 = acc[m2 * 4 + 2 * p];
                float* c1 = acc[m2 * 4 + 2 * p + 1];
                mma16(c0, ah, &bhf[p][0]);
                mma16(c1, ah, &bhf[p][2]);
                if (TERMS == 2) {
                    mma16(c0, ah, &bmf[p][0]);
                    mma16(c1, ah, &bmf[p][2]);
                }
            }
        }
        __syncthreads();
    }

    // ---- epilogue ----
#pragma unroll
    for (int m2 = 0; m2 < 4; m2++) {
        const int row0 = brow0 + wm + m2 * 16 + g;
#pragma unroll
        for (int nn = 0; nn < 4; nn++) {
            const int col = bcol0 + wn + nn * 8 + 2 * q;
            if (col < N) {
                const float* c = acc[m2 * 4 + nn];
                float o0 = c[0], o1 = c[1], o2 = c[2], o3 = c[3];
                if (mode == 1) {
                    o0 += bias[col]; o2 += bias[col];
                    o1 += bias[col + 1]; o3 += bias[col + 1];
                } else if (mode == 2) {
                    const float i0 = 2.f * bias[col], i1 = 2.f * bias[col + 1];
                    o0 += i0; o2 += i0; o1 += i1; o3 += i1;
                    o0 = (o0 > 20.f) ? o0 : log1pf(expf(o0));
                    o1 = (o1 > 20.f) ? o1 : log1pf(expf(o1));
                    o2 = (o2 > 20.f) ? o2 : log1pf(expf(o2));
                    o3 = (o3 > 20.f) ? o3 : log1pf(expf(o3));
                }
                *(float2*)&C[(size_t)row0 * ldc + col] = make_float2(o0, o1);
                *(float2*)&C[(size_t)(row0 + 8) * ldc + col] = make_float2(o2, o3);
            }
        }
    }
}

// ---------------- depthwise conv (k=4, SAME: pad_l=1, pad_r=2) + SiLU -------
__global__ void conv_silu(const float* __restrict__ in, int istride,
                          const float* __restrict__ w, const float* __restrict__ bias,
                          float* __restrict__ out, int ostride)
{
    const int idx = blockIdx.x * blockDim.x + threadIdx.x;
    const int row = idx >> 10;
    const int c   = idx & 1023;
    const int l   = row & (LEN - 1);

    float acc = bias[c];
#pragma unroll
    for (int j = 0; j < 4; j++) {
        const int ll = l - 1 + j;
        if ((unsigned)ll < (unsigned)LEN)
            acc = fmaf(w[j * DHALF + c], in[(size_t)(row - 1 + j) * istride + c], acc);
    }
    const float s = 1.f / (1.f + expf(-acc));
    out[(size_t)row * ostride + c] = acc * s;
}

// ---------------- selective scan: 4 threads per (b,d), n-quad each ----------
__global__ void scan_k(const float* __restrict__ u, const float* __restrict__ dl,
                       const float* __restrict__ xdbl, const float* __restrict__ Dv,
                       float* __restrict__ y)
{
    const int tid = blockIdx.x * blockDim.x + threadIdx.x;
    const int j  = tid & 3;
    const int bd = tid >> 2;
    const int d  = bd & (DHALF - 1);
    const int b  = bd >> 10;
    const float Dd = Dv[d];

    float h0 = 0.f, h1 = 0.f, h2 = 0.f, h3 = 0.f;
    size_t row = (size_t)b * LEN;
    for (int t = 0; t < LEN; t++, row++) {
        const float dval = dl[row * DHALF + d];
        const float uu   = u[row * DHALF + d];
        const float4 Bq = __ldg((const float4*)(xdbl + row * XDBL_W + 64) + j);
        const float4 Cq = __ldg((const float4*)(xdbl + row * XDBL_W + 80) + j);

        const float e1 = __expf(-dval);
        const float e2 = e1 * e1, e4 = e2 * e2, e8 = e4 * e4;
        float pj = (j & 1) ? e4 : 1.f;
        if (j & 2) pj *= e8;
        const float p0 = pj * e1;
        const float p1 = p0 * e1, p2 = p1 * e1, p3 = p2 * e1;
        const float xd = dval * uu;

        h0 = fmaf(p0, h0, xd * Bq.x);
        h1 = fmaf(p1, h1, xd * Bq.y);
        h2 = fmaf(p2, h2, xd * Bq.z);
        h3 = fmaf(p3, h3, xd * Bq.w);

        float cy = fmaf(h0, Cq.x, h1 * Cq.y) + fmaf(h2, Cq.z, h3 * Cq.w);
        cy += __shfl_xor_sync(0xffffffffu, cy, 1);
        cy += __shfl_xor_sync(0xffffffffu, cy, 2);
        if (j == 0) y[row * DINNER + d] = cy + uu * Dd;
    }
}

// ---------------- launch --------------------------------------------------
extern "C" void kernel_launch(void* const* d_in, const int* in_sizes, int n_in,
                              void* d_out, int out_size)
{
    const float* x       = (const float*)d_in[0];
    const float* W_in    = (const float*)d_in[1];
    const float* conv_xw = (const float*)d_in[2];
    const float* conv_xb = (const float*)d_in[3];
    const float* conv_zw = (const float*)d_in[4];
    const float* conv_zb = (const float*)d_in[5];
    const float* W_xdbl  = (const float*)d_in[6];
    const float* W_dt    = (const float*)d_in[7];
    const float* inv_dt  = (const float*)d_in[8];
    const float* Dvec    = (const float*)d_in[9];
    const float* W_out   = (const float*)d_in[10];
    const float* b_out   = (const float*)d_in[11];
    float* out = (float*)d_out;

    float *p_xz, *p_u, *p_ycat, *p_xdbl, *p_delta;
    cudaGetSymbolAddress((void**)&p_xz,    g_xz);
    cudaGetSymbolAddress((void**)&p_u,     g_u);
    cudaGetSymbolAddress((void**)&p_ycat,  g_ycat);
    cudaGetSymbolAddress((void**)&p_xdbl,  g_xdbl);
    cudaGetSymbolAddress((void**)&p_delta, g_delta);

    __half *w_in_h, *w_in_m, *w_xd_h, *w_xd_m, *w_dt_h, *w_dt_m, *w_out_h, *w_out_m;
    cudaGetSymbolAddress((void**)&w_in_h,  g_Win_h);
    cudaGetSymbolAddress((void**)&w_in_m,  g_Win_m);
    cudaGetSymbolAddress((void**)&w_xd_h,  g_Wxd_h);
    cudaGetSymbolAddress((void**)&w_xd_m,  g_Wxd_m);
    cudaGetSymbolAddress((void**)&w_dt_h,  g_Wdt_h);
    cudaGetSymbolAddress((void**)&w_dt_m,  g_Wdt_m);
    cudaGetSymbolAddress((void**)&w_out_h, g_Wout_h);
    cudaGetSymbolAddress((void**)&w_out_m, g_Wout_m);

    const dim3 tsb(32, 8);

    // 0) pre-split + transpose all weight matrices to [N][K] fp16 hi/mid
    tsplit<<<dim3(DINNER / 32, DMODEL / 32), tsb>>>(W_in,   w_in_h,  w_in_m,  DMODEL, DINNER);
    tsplit<<<dim3(XDBL_W / 32, DHALF / 32),  tsb>>>(W_xdbl, w_xd_h,  w_xd_m,  DHALF,  XDBL_W);
    tsplit<<<dim3(DHALF / 32, DTRANK / 32),  tsb>>>(W_dt,   w_dt_h,  w_dt_m,  DTRANK, DHALF);
    tsplit<<<dim3(DMODEL / 32, DINNER / 32), tsb>>>(W_out,  w_out_h, w_out_m, DINNER, DMODEL);

    const int elemBlocks = (NROWS * DHALF) / 256;

    // 1) xz = x @ W_in   (8192 x 2048 x 1024)  -- single-term fp16
    gemm_f2<1><<<dim3(DINNER / BN, NROWS / BM), 256>>>(
        x, w_in_h, w_in_m, p_xz, nullptr, DINNER, DMODEL, DMODEL, DINNER, 0);

    // 2) u = silu(conv(xs));  3) ycat[:,1024:] = silu(conv(z))
    conv_silu<<<elemBlocks, 256>>>(p_xz,         DINNER, conv_xw, conv_xb, p_u,            DHALF);
    conv_silu<<<elemBlocks, 256>>>(p_xz + DHALF, DINNER, conv_zw, conv_zb, p_ycat + DHALF, DINNER);

    // 4) x_dbl = u @ W_xdbl   (8192 x 96 x 1024)  -- 2-term (feeds scan B/C/dt)
    gemm_f2<2><<<dim3(1, NROWS / BM), 256>>>(
        p_u, w_xd_h, w_xd_m, p_xdbl, nullptr, XDBL_W, DHALF, DHALF, XDBL_W, 0);

    // 5) delta = softplus(dt_low @ W_dt + 2*inv_dt)  -- 2-term, fused epilogue
    gemm_f2<2><<<dim3(DHALF / BN, NROWS / BM), 256>>>(
        p_xdbl, w_dt_h, w_dt_m, p_delta, inv_dt, DHALF, DTRANK, XDBL_W, DHALF, 2);

    // 6) selective scan -> ycat[:, :1024]
    scan_k<<<64, 256>>>(p_u, p_delta, p_xdbl, Dvec, p_ycat);

    // 7) out = ycat @ W_out + b_out   (8192 x 1024 x 2048)  -- single-term fp16
    gemm_f2<1><<<dim3(DMODEL / BN, NROWS / BM), 256>>>(
        p_ycat, w_out_h, w_out_m, out, b_out, DMODEL, DINNER, DINNER, DMODEL, 1);
}